// round 4
// baseline (speedup 1.0000x reference)
#include <cuda_runtime.h>
#include <cuda_bf16.h>
#include <math.h>
#include <stdint.h>

// Problem constants
#define BATCH 2
#define SEQ   2048
#define EMB   2048
#define HEADS 16
#define HDIM  128

// Scratch buffers (allocation-free rule: __device__ globals)
__device__ float g_q[BATCH * SEQ * EMB];
__device__ float g_k[BATCH * SEQ * EMB];
__device__ float g_v[BATCH * SEQ * EMB];
__device__ float g_att[BATCH * SEQ * EMB];   // attention out (tf32-rounded)
__device__ float g_actr[BATCH * SEQ * EMB];  // tf32-rounded activations
__device__ float g_wq[EMB * EMB];
__device__ float g_wk[EMB * EMB];
__device__ float g_wv[EMB * EMB];
__device__ float g_wo[EMB * EMB];

// ---------------------------------------------------------------------------
// helpers
// ---------------------------------------------------------------------------
__device__ __forceinline__ uint32_t smem_u32(const void* p) {
    uint32_t a;
    asm("{ .reg .u64 t; cvta.to.shared.u64 t, %1; cvt.u32.u64 %0, t; }"
        : "=r"(a) : "l"(p));
    return a;
}

__device__ __forceinline__ float rna_tf32(float x) {
    float r;
    asm("cvt.rna.tf32.f32 %0, %1;" : "=f"(r) : "f"(x));
    return r;
}

__device__ __forceinline__ float ex2(float x) {
    float r;
    asm("ex2.approx.ftz.f32 %0, %1;" : "=f"(r) : "f"(x));
    return r;
}

#define CP_ASYNC16(saddr, gaddr) \
    asm volatile("cp.async.ca.shared.global [%0], [%1], 16;" \
                 :: "r"(saddr), "l"(gaddr) : "memory")
#define CP_COMMIT() asm volatile("cp.async.commit_group;" ::: "memory")
#define CP_WAIT(n)  asm volatile("cp.async.wait_group %0;" :: "n"(n) : "memory")

#define MMA_TF32(c, a0, a1, a2, a3, b0, b1) \
    asm volatile("mma.sync.aligned.m16n8k8.row.col.f32.tf32.tf32.f32 " \
                 "{%0,%1,%2,%3}, {%4,%5,%6,%7}, {%8,%9}, {%0,%1,%2,%3};" \
                 : "+f"((c)[0]), "+f"((c)[1]), "+f"((c)[2]), "+f"((c)[3]) \
                 : "r"(a0), "r"(a1), "r"(a2), "r"(a3), "r"(b0), "r"(b1))

// ---------------------------------------------------------------------------
// tf32 rounding pass
// ---------------------------------------------------------------------------
__global__ __launch_bounds__(256)
void round_tf32_kernel(const float* __restrict__ in, float* __restrict__ out, int n4) {
    int i = blockIdx.x * 256 + threadIdx.x;
    if (i >= n4) return;
    float4 v = ((const float4*)in)[i];
    v.x = rna_tf32(v.x); v.y = rna_tf32(v.y);
    v.z = rna_tf32(v.z); v.w = rna_tf32(v.w);
    ((float4*)out)[i] = v;
}

// ---------------------------------------------------------------------------
// tf32 mma.sync GEMM (NT): C[M,N] = A[M,K] * B[N,K]^T (unchanged from R3)
// ---------------------------------------------------------------------------
#define BM 128
#define BN 128
#define BK 32
#define SROW 36
#define TILE_F (128 * SROW)
#define STAGE_F (2 * TILE_F)
#define STAGE_B (STAGE_F * 4)
#define GM_SMEM (2 * STAGE_B)
#define NK (EMB / BK)

__global__ __launch_bounds__(256, 1)
void gemm_tf32(const float* __restrict__ A, const float* __restrict__ B,
               float* __restrict__ C) {
    extern __shared__ float smf[];
    const uint32_t sb = smem_u32(smf);

    const int tid = threadIdx.x;
    const int wid = tid >> 5;
    const int lane = tid & 31;
    const int gid = lane >> 2;
    const int tig = lane & 3;
    const int wm = wid >> 2;
    const int wn = wid & 3;
    const int bm = blockIdx.y * BM;
    const int bn = blockIdx.x * BN;

    float acc[4][4][4];
#pragma unroll
    for (int mi = 0; mi < 4; mi++)
#pragma unroll
        for (int ni = 0; ni < 4; ni++)
#pragma unroll
            for (int q = 0; q < 4; q++) acc[mi][ni][q] = 0.0f;

    auto issue_stage = [&](int kt, int stage) {
#pragma unroll
        for (int c = 0; c < 4; c++) {
            int id = tid + c * 256;
            int row = id >> 3;
            int cg = id & 7;
            uint32_t soff = (uint32_t)(row * SROW + cg * 4) * 4u;
            uint32_t saA = sb + stage * STAGE_B + soff;
            uint32_t saB = saA + TILE_F * 4;
            const float* gaA = A + (size_t)(bm + row) * EMB + kt * BK + cg * 4;
            const float* gaB = B + (size_t)(bn + row) * EMB + kt * BK + cg * 4;
            CP_ASYNC16(saA, gaA);
            CP_ASYNC16(saB, gaB);
        }
        CP_COMMIT();
    };

    issue_stage(0, 0);
    issue_stage(1, 1);

    for (int kt = 0; kt < NK; kt++) {
        const int s = kt & 1;
        if (kt + 1 < NK) { CP_WAIT(1); } else { CP_WAIT(0); }
        __syncthreads();

        const float* As = smf + s * STAGE_F;
        const float* Bs = As + TILE_F;
        const int am0 = wm * 64;
        const int bn0 = wn * 32;

#pragma unroll
        for (int ks = 0; ks < 4; ks++) {
            const int k0 = ks * 8;
            uint32_t a[4][4];
#pragma unroll
            for (int mi = 0; mi < 4; mi++) {
                const int r0 = am0 + mi * 16 + gid;
                a[mi][0] = __float_as_uint(As[r0 * SROW + k0 + tig]);
                a[mi][1] = __float_as_uint(As[(r0 + 8) * SROW + k0 + tig]);
                a[mi][2] = __float_as_uint(As[r0 * SROW + k0 + tig + 4]);
                a[mi][3] = __float_as_uint(As[(r0 + 8) * SROW + k0 + tig + 4]);
            }
            uint32_t b[4][2];
#pragma unroll
            for (int ni = 0; ni < 4; ni++) {
                const int n0 = bn0 + ni * 8 + gid;
                b[ni][0] = __float_as_uint(Bs[n0 * SROW + k0 + tig]);
                b[ni][1] = __float_as_uint(Bs[n0 * SROW + k0 + tig + 4]);
            }
#pragma unroll
            for (int mi = 0; mi < 4; mi++)
#pragma unroll
                for (int ni = 0; ni < 4; ni++)
                    MMA_TF32(acc[mi][ni], a[mi][0], a[mi][1], a[mi][2], a[mi][3],
                             b[ni][0], b[ni][1]);
        }
        __syncthreads();
        if (kt + 2 < NK) issue_stage(kt + 2, s);
    }

#pragma unroll
    for (int mi = 0; mi < 4; mi++) {
        const int r0 = bm + wm * 64 + mi * 16 + gid;
#pragma unroll
        for (int ni = 0; ni < 4; ni++) {
            const int c0 = bn + wn * 32 + ni * 8 + tig * 2;
            float2 w0; w0.x = acc[mi][ni][0]; w0.y = acc[mi][ni][1];
            float2 w1; w1.x = acc[mi][ni][2]; w1.y = acc[mi][ni][3];
            *(float2*)(C + (size_t)r0 * EMB + c0) = w0;
            *(float2*)(C + (size_t)(r0 + 8) * EMB + c0) = w1;
        }
    }
}

// ---------------------------------------------------------------------------
// xpos rotary on q and k (in place).
// ---------------------------------------------------------------------------
__global__ __launch_bounds__(256)
void xpos_kernel() {
    int idx = blockIdx.x * 256 + threadIdx.x;
    int pair = idx & 63;
    int h = (idx >> 6) & (HEADS - 1);
    int bs = idx >> 10;
    int s = bs & (SEQ - 1);

    float seq = (float)(s - SEQ / 2) * (1.0f / 512.0f);
    float dr = 2.0f * (float)(pair + 1);
    float theta = powf(1.0e-4f, dr * (1.0f / 128.0f));
    float zeta = (dr * (1.0f / 64.0f) + 51.2f) * (1.0f / 52.2f);
    float ang = seq * theta;
    float c = cosf(ang);
    float sn = sinf(ang);
    float t = powf(zeta, seq);
    float it = 1.0f / t;

    size_t base = (size_t)bs * EMB + h * HDIM + pair * 2;
    float2 qv = *(float2*)(g_q + base);
    float2 kv = *(float2*)(g_k + base);
    float2 qo, ko;
    qo.x = (qv.x * c - qv.y * sn) * t;
    qo.y = (qv.y * c + qv.x * sn) * t;
    ko.x = (kv.x * c - kv.y * sn) * it;
    ko.y = (kv.y * c + kv.x * sn) * it;
    *(float2*)(g_q + base) = qo;
    *(float2*)(g_k + base) = ko;
}

// ---------------------------------------------------------------------------
// Causal flash attention, fp32, 4-key blocked softmax (MUFU-minimized).
// Block = 512 threads = 128 query rows x 4-thread groups (32 dims each).
// ---------------------------------------------------------------------------
__global__ __launch_bounds__(512, 1)
void attn_kernel() {
    extern __shared__ float smf[];
    float4* Ks4 = (float4*)smf;
    float4* Vs4 = (float4*)(smf + 64 * 128);

    const int bid = blockIdx.x;
    const int qt = (SEQ / 128 - 1) - (bid >> 5);
    const int bh = bid & 31;
    const int b = bh >> 4;
    const int h = bh & (HEADS - 1);

    const int tid = threadIdx.x;
    const int rloc = tid >> 2;
    const int g = tid & 3;
    const int r = qt * 128 + rloc;
    const unsigned gmask = 0xFu << ((tid & 31) & ~3);

    // q fragment, pre-scaled by (1/sqrt(D)) * log2(e) so scores are log2-domain
    const float qscale = 0.08838834764831845f * 1.4426950408889634f;
    const float* qbase = g_q + ((size_t)b * SEQ + r) * EMB + h * HDIM + g * 32;
    float4 q4[8];
#pragma unroll
    for (int i = 0; i < 8; i++) {
        float4 v = ((const float4*)qbase)[i];
        v.x *= qscale; v.y *= qscale; v.z *= qscale; v.w *= qscale;
        q4[i] = v;
    }

    float4 o4[8];
#pragma unroll
    for (int i = 0; i < 8; i++) o4[i] = make_float4(0.f, 0.f, 0.f, 0.f);
    float m = -1.0e30f, l = 0.0f;

    const float* kg = g_k + (size_t)b * SEQ * EMB + h * HDIM;
    const float* vg = g_v + (size_t)b * SEQ * EMB + h * HDIM;

    const int nkt = qt * 2 + 2;
    for (int kt = 0; kt < nkt; kt++) {
        __syncthreads();
#pragma unroll
        for (int i = 0; i < 4; i++) {
            int id = tid + i * 512;
            int row = id >> 5;
            int c4 = id & 31;
            size_t goff = (size_t)(kt * 64 + row) * EMB + c4 * 4;
            Ks4[row * 32 + c4] = *(const float4*)(kg + goff);
            Vs4[row * 32 + c4] = *(const float4*)(vg + goff);
        }
        __syncthreads();

        int jmax = r - kt * 64 + 1;
        if (jmax > 64) jmax = 64;

        for (int j0 = 0; j0 < jmax; j0 += 4) {
            // partial dots for keys j0..j0+3 over this thread's 32 dims
            float pp[4];
#pragma unroll
            for (int jj = 0; jj < 4; jj++) {
                const float4* krow = Ks4 + (j0 + jj) * 32 + g * 8;
                float p0 = 0.f, p1 = 0.f, p2 = 0.f, p3 = 0.f;
#pragma unroll
                for (int i = 0; i < 8; i++) {
                    float4 kv = krow[i];
                    p0 = fmaf(q4[i].x, kv.x, p0);
                    p1 = fmaf(q4[i].y, kv.y, p1);
                    p2 = fmaf(q4[i].z, kv.z, p2);
                    p3 = fmaf(q4[i].w, kv.w, p3);
                }
                pp[jj] = (p0 + p1) + (p2 + p3);
            }
            // transpose-reduce: thread g ends with full dot for key j0+g
            float x0 = __shfl_xor_sync(gmask, pp[0], 1);
            float x1 = __shfl_xor_sync(gmask, pp[1], 1);
            float x2 = __shfl_xor_sync(gmask, pp[2], 1);
            float x3 = __shfl_xor_sync(gmask, pp[3], 1);
            bool odd = (g & 1);
            float ka = odd ? (pp[1] + x1) : (pp[0] + x0);
            float kb = odd ? (pp[3] + x3) : (pp[2] + x2);
            float ya = __shfl_xor_sync(gmask, ka, 2);
            float yb = __shfl_xor_sync(gmask, kb, 2);
            float s = (g & 2) ? (kb + yb) : (ka + ya);
            // causal mask: this thread's key is j0+g
            if (j0 + g >= jmax) s = -1.0e30f;

            // group max (2 shfl), online softmax in log2 domain
            float mx = fmaxf(s, __shfl_xor_sync(gmask, s, 1));
            mx = fmaxf(mx, __shfl_xor_sync(gmask, mx, 2));
            float mn = fmaxf(m, mx);
            float cf = ex2(m - mn);
            float p = ex2(s - mn);
            m = mn;

            // gather all 4 p values (by xor offset, no dynamic indexing)
            float q1 = __shfl_xor_sync(gmask, p, 1);
            float q2 = __shfl_xor_sync(gmask, p, 2);
            float q3 = __shfl_xor_sync(gmask, q1, 2);
            l = l * cf + ((p + q1) + (q2 + q3));

            const float4* v0 = Vs4 + (j0 + g) * 32 + g * 8;
            const float4* v1 = Vs4 + (j0 + (g ^ 1)) * 32 + g * 8;
            const float4* v2 = Vs4 + (j0 + (g ^ 2)) * 32 + g * 8;
            const float4* v3 = Vs4 + (j0 + (g ^ 3)) * 32 + g * 8;
#pragma unroll
            for (int i = 0; i < 8; i++) {
                float4 a0 = v0[i], a1 = v1[i], a2 = v2[i], a3 = v3[i];
                float4 oo = o4[i];
                oo.x = oo.x * cf; oo.y = oo.y * cf;
                oo.z = oo.z * cf; oo.w = oo.w * cf;
                oo.x = fmaf(p, a0.x, oo.x); oo.y = fmaf(p, a0.y, oo.y);
                oo.z = fmaf(p, a0.z, oo.z); oo.w = fmaf(p, a0.w, oo.w);
                oo.x = fmaf(q1, a1.x, oo.x); oo.y = fmaf(q1, a1.y, oo.y);
                oo.z = fmaf(q1, a1.z, oo.z); oo.w = fmaf(q1, a1.w, oo.w);
                oo.x = fmaf(q2, a2.x, oo.x); oo.y = fmaf(q2, a2.y, oo.y);
                oo.z = fmaf(q2, a2.z, oo.z); oo.w = fmaf(q2, a2.w, oo.w);
                oo.x = fmaf(q3, a3.x, oo.x); oo.y = fmaf(q3, a3.y, oo.y);
                oo.z = fmaf(q3, a3.z, oo.z); oo.w = fmaf(q3, a3.w, oo.w);
                o4[i] = oo;
            }
        }
    }

    float inv = 1.0f / l;
    float* ob = g_att + ((size_t)b * SEQ + r) * EMB + h * HDIM + g * 32;
#pragma unroll
    for (int i = 0; i < 8; i++) {
        float4 w;
        w.x = rna_tf32(o4[i].x * inv);
        w.y = rna_tf32(o4[i].y * inv);
        w.z = rna_tf32(o4[i].z * inv);
        w.w = rna_tf32(o4[i].w * inv);
        ((float4*)ob)[i] = w;
    }
}

// ---------------------------------------------------------------------------
// Launch. Order: 5 rounding kernels first so ncu (-s 5 -c 1) captures the
// first GEMM as the 6th launch.
// ---------------------------------------------------------------------------
extern "C" void kernel_launch(void* const* d_in, const int* in_sizes, int n_in,
                              void* d_out, int out_size) {
    const float* act = (const float*)d_in[0];
    const float* Wq  = (const float*)d_in[1];
    const float* Wk  = (const float*)d_in[2];
    const float* Wv  = (const float*)d_in[3];
    const float* Wo  = (const float*)d_in[4];
    float* out = (float*)d_out;

    float *qp, *kp, *vp, *ap, *actr, *wq, *wk, *wv, *wo;
    cudaGetSymbolAddress((void**)&qp, g_q);
    cudaGetSymbolAddress((void**)&kp, g_k);
    cudaGetSymbolAddress((void**)&vp, g_v);
    cudaGetSymbolAddress((void**)&ap, g_att);
    cudaGetSymbolAddress((void**)&actr, g_actr);
    cudaGetSymbolAddress((void**)&wq, g_wq);
    cudaGetSymbolAddress((void**)&wk, g_wk);
    cudaGetSymbolAddress((void**)&wv, g_wv);
    cudaGetSymbolAddress((void**)&wo, g_wo);

    cudaFuncSetAttribute(gemm_tf32, cudaFuncAttributeMaxDynamicSharedMemorySize, GM_SMEM);
    cudaFuncSetAttribute(attn_kernel, cudaFuncAttributeMaxDynamicSharedMemorySize,
                         64 * 128 * 4 * 2);

    const int nw4 = EMB * EMB / 4;
    const int na4 = BATCH * SEQ * EMB / 4;
    dim3 ggrid(EMB / BN, BATCH * SEQ / BM);

    // launches 1-5: rounding
    round_tf32_kernel<<<(na4 + 255) / 256, 256>>>(act, actr, na4);
    round_tf32_kernel<<<(nw4 + 255) / 256, 256>>>(Wq, wq, nw4);
    round_tf32_kernel<<<(nw4 + 255) / 256, 256>>>(Wk, wk, nw4);
    round_tf32_kernel<<<(nw4 + 255) / 256, 256>>>(Wv, wv, nw4);
    round_tf32_kernel<<<(nw4 + 255) / 256, 256>>>(Wo, wo, nw4);

    // launch 6: first GEMM (ncu capture target)
    gemm_tf32<<<ggrid, 256, GM_SMEM>>>(actr, wq, qp);
    gemm_tf32<<<ggrid, 256, GM_SMEM>>>(actr, wk, kp);
    gemm_tf32<<<ggrid, 256, GM_SMEM>>>(actr, wv, vp);

    int nrot = BATCH * SEQ * HEADS * 64;
    xpos_kernel<<<nrot / 256, 256>>>();

    attn_kernel<<<BATCH * HEADS * (SEQ / 128), 512, 64 * 128 * 4 * 2>>>();

    gemm_tf32<<<ggrid, 256, GM_SMEM>>>(ap, wo, out);
}